// round 12
// baseline (speedup 1.0000x reference)
#include <cuda_runtime.h>
#include <cuda_bf16.h>
#include <cstdint>

// Problem constants
#define B_   16
#define C_   256
#define HW_  1024
#define K_   8192
#define N_   16384            // tokens
#define NQE  4194304          // qe elems

// Tiling
#define TM 128                 // tokens per CTA
#define TN 128                 // codes per CTA
#define NCHUNK 8               // chunks of 32 k (= 8 packed words)
#define NCAND 256              // candidates per token
#define MARGIN 6.0f            // exact-rerank margin (covers int8 quant noise)
#define QS 26.0f               // int8 quant scale
#define NEG2INV (-2.0f / (QS * QS))

// smem (uint32 units). A: [kw 8][m 128] stride 136 (banks 8*tg+g distinct)
// B: [nr 128][kw 8] stride 12 (banks 12*g+tg distinct)
#define AST 136
#define A_U32 (8 * AST)                 // 1088
#define BST 12
#define B_U32 (128 * BST)               // 1536
#define STAGE_U32 (A_U32 + B_U32)       // 2624
#define STAGE_BYTES (STAGE_U32 * 4)     // 10496
#define SMEM_BYTES (2 * STAGE_BYTES)    // 20992

// Scratch
__device__ unsigned long long g_cand[(size_t)N_ * NCAND];   // 32MB
__device__ uint32_t g_xq[(size_t)B_ * 64 * HW_];            // 4MB  int8x4 x, [b][kw][t]
__device__ uint32_t g_cbq[(size_t)K_ * 64];                 // 2MB  int8x4 cb, [n][kw]
__device__ unsigned int g_idx[N_];
__device__ float g_cnorm[K_];
__device__ float g_partial[B_ * C_];

__device__ __forceinline__ unsigned int fkey(float f) {
    unsigned int b = __float_as_uint(f);
    return (b & 0x80000000u) ? ~b : (b | 0x80000000u);
}
__device__ __forceinline__ float unfkey(unsigned int k) {
    unsigned int b = (k & 0x80000000u) ? (k & 0x7FFFFFFFu) : ~k;
    return __uint_as_float(b);
}
__device__ __forceinline__ int q8(float v) {
    int q = __float2int_rn(v * QS);
    return max(-127, min(127, q));
}
__device__ __forceinline__ uint32_t pack4(float a, float b, float c, float d) {
    return (uint32_t)(q8(a) & 0xFF) | ((uint32_t)(q8(b) & 0xFF) << 8) |
           ((uint32_t)(q8(c) & 0xFF) << 16) | ((uint32_t)(q8(d) & 0xFF) << 24);
}
__device__ __forceinline__ uint32_t smem_u32(const void* p) {
    uint32_t a;
    asm("{ .reg .u64 t; cvta.to.shared.u64 t, %1; cvt.u32.u64 %0, t; }"
        : "=r"(a) : "l"(p));
    return a;
}
__device__ __forceinline__ void cp16(uint32_t dst, const void* src) {
    asm volatile("cp.async.cg.shared.global [%0], [%1], 16;"
                 :: "r"(dst), "l"(src));
}

#define MMA_S8(D, A, B0, B1)                                                \
    asm volatile("mma.sync.aligned.m16n8k32.row.col.s32.s8.s8.s32 "         \
        "{%0,%1,%2,%3},{%4,%5,%6,%7},{%8,%9},{%0,%1,%2,%3};"                \
        : "+r"((D)[0]), "+r"((D)[1]), "+r"((D)[2]), "+r"((D)[3])            \
        : "r"((A)[0]), "r"((A)[1]), "r"((A)[2]), "r"((A)[3]),               \
          "r"(B0), "r"(B1))

// ---------------------------------------------------------------------------
// Kernel 0a: quantize x -> int8x4 words, layout [b][kw 64][t 1024].
// One block per (b, kw): reads 4 channel rows, packs along k. Coalesced.
__global__ void pconv_x_kernel(const float* __restrict__ x) {
    const int blk = blockIdx.x;              // b*64 + kw
    const int b = blk >> 6, kw = blk & 63;
    const float4* r0 = (const float4*)(x + ((size_t)(b * C_ + 4 * kw)) * HW_);
    const float4* r1 = (const float4*)(x + ((size_t)(b * C_ + 4 * kw + 1)) * HW_);
    const float4* r2 = (const float4*)(x + ((size_t)(b * C_ + 4 * kw + 2)) * HW_);
    const float4* r3 = (const float4*)(x + ((size_t)(b * C_ + 4 * kw + 3)) * HW_);
    const int t4 = threadIdx.x;              // 256 threads x 4 tokens
    float4 v0 = r0[t4], v1 = r1[t4], v2 = r2[t4], v3 = r3[t4];
    uint4 o;
    o.x = pack4(v0.x, v1.x, v2.x, v3.x);
    o.y = pack4(v0.y, v1.y, v2.y, v3.y);
    o.z = pack4(v0.z, v1.z, v2.z, v3.z);
    o.w = pack4(v0.w, v1.w, v2.w, v3.w);
    ((uint4*)(g_xq + (size_t)blk * HW_))[t4] = o;
}

// Kernel 0b: quantize codebook -> int8x4 [n][kw 64], fused with exact cnorm.
__global__ void pconv_cb_kernel(const float* __restrict__ cb) {
    int code = blockIdx.x * 8 + (threadIdx.x >> 5);
    int lane = threadIdx.x & 31;
    const float4* row = (const float4*)(cb + (size_t)code * C_);
    uint32_t* orow = g_cbq + (size_t)code * 64;
    float s = 0.0f;
#pragma unroll
    for (int r = 0; r < 2; r++) {
        float4 v = row[lane + 32 * r];
        s += v.x * v.x + v.y * v.y + v.z * v.z + v.w * v.w;
        orow[lane + 32 * r] = pack4(v.x, v.y, v.z, v.w);
    }
#pragma unroll
    for (int off = 16; off; off >>= 1)
        s += __shfl_xor_sync(0xFFFFFFFFu, s, off);
    if (lane == 0) g_cnorm[code] = s;
}

// ---------------------------------------------------------------------------
// Kernel 2: int8 screening GEMM (m16n8k32), cp.async loads, top-2 per n-warp
// per token. grid=(128,64), block=256 (4m x 2n warps).
__global__ void __launch_bounds__(256, 2)
argmin_mma_kernel() {
    extern __shared__ uint32_t smemu[];
    __shared__ float cnS[TN];

    const int tid = threadIdx.x;
    const int wid = tid >> 5;
    const int lane = tid & 31;
    const int g  = lane >> 2;
    const int tg = lane & 3;
    const int m0w = (wid & 3) * 32;
    const int n0w = (wid >> 2) * 64;

    const int n0tok = blockIdx.x * TM;
    const int b   = n0tok >> 10;
    const int hw0 = n0tok & 1023;
    const int j0  = blockIdx.y * TN;

    if (tid < TN) cnS[tid] = g_cnorm[j0 + tid];

    const uint32_t sbase = smem_u32(smemu);
    const uint32_t* xqB = g_xq + (size_t)b * (64 * HW_) + hw0;  // + kw*HW_ + t

    int d[2][8][4];
#pragma unroll
    for (int i = 0; i < 2; i++)
#pragma unroll
        for (int j = 0; j < 8; j++)
#pragma unroll
            for (int e = 0; e < 4; e++) d[i][j][e] = 0;

    auto fill = [&](int k, int stg) {
        uint32_t As = sbase + (uint32_t)(stg * STAGE_BYTES);
        uint32_t Bs = As + A_U32 * 4;
        // A tile: 8 kw-rows x 128 words = 256 granules (1 per thread)
        {
            int row = tid >> 5, c16 = tid & 31;
            cp16(As + (uint32_t)(row * (AST * 4) + c16 * 16),
                 xqB + (size_t)(k * 8 + row) * HW_ + c16 * 4);
        }
        // B tile: 128 n-rows x 8 words (2 granules) = 256 granules
        {
            int nr = tid >> 1, c2 = tid & 1;
            cp16(Bs + (uint32_t)(nr * (BST * 4) + c2 * 16),
                 g_cbq + (size_t)(j0 + nr) * 64 + k * 8 + c2 * 4);
        }
        asm volatile("cp.async.commit_group;" ::: "memory");
    };

    auto mma_stage = [&](int stg) {
        const uint32_t* As = smemu + stg * STAGE_U32;
        const uint32_t* Bs = As + A_U32;
        uint32_t a[2][4];
#pragma unroll
        for (int dm = 0; dm < 2; dm++) {
            int mc = m0w + 16 * dm + g;
            a[dm][0] = As[tg * AST + mc];
            a[dm][1] = As[tg * AST + mc + 8];
            a[dm][2] = As[(tg + 4) * AST + mc];
            a[dm][3] = As[(tg + 4) * AST + mc + 8];
        }
#pragma unroll
        for (int dn = 0; dn < 8; dn++) {
            int nr = n0w + 8 * dn + g;
            uint32_t b0 = Bs[nr * BST + tg];
            uint32_t b1 = Bs[nr * BST + tg + 4];
            MMA_S8(d[0][dn], a[0], b0, b1);
            MMA_S8(d[1][dn], a[1], b0, b1);
        }
    };

    fill(0, 0);
    fill(1, 1);
#pragma unroll 1
    for (int k = 0; k < NCHUNK; k++) {
        asm volatile("cp.async.wait_group 1;" ::: "memory");
        __syncthreads();
        mma_stage(k & 1);
        __syncthreads();
        if (k + 2 < NCHUNK) fill(k + 2, k & 1);
        else asm volatile("cp.async.commit_group;" ::: "memory");
    }

    // epilogue: per n-warp top-2 per token row, race-free candidate writes
#pragma unroll
    for (int dm = 0; dm < 2; dm++) {
#pragma unroll
        for (int h = 0; h < 2; h++) {
            unsigned long long p1 = 0xFFFFFFFFFFFFFFFFull;
            unsigned long long p2 = 0xFFFFFFFFFFFFFFFFull;
#pragma unroll
            for (int dn = 0; dn < 8; dn++) {
#pragma unroll
                for (int e = 0; e < 2; e++) {
                    int col = n0w + 8 * dn + 2 * tg + e;
                    float sc = fmaf(NEG2INV,
                                    __int2float_rn(d[dm][dn][2 * h + e]),
                                    cnS[col]);
                    unsigned long long p =
                        ((unsigned long long)fkey(sc) << 32) |
                        (unsigned int)(j0 + col);
                    if (p < p1) { p2 = p1; p1 = p; }
                    else if (p < p2) { p2 = p; }
                }
            }
#pragma unroll
            for (int off = 1; off <= 2; off <<= 1) {
                unsigned long long q1 = __shfl_xor_sync(0xFFFFFFFFu, p1, off);
                unsigned long long q2 = __shfl_xor_sync(0xFFFFFFFFu, p2, off);
                if (q1 < p1) { p2 = (p1 < q2) ? p1 : q2; p1 = q1; }
                else         { p2 = (p2 < q1) ? p2 : q1; }
            }
            if (tg == 0) {
                int tok = n0tok + m0w + 16 * dm + 8 * h + g;
                size_t base = (size_t)tok * NCAND + blockIdx.y * 4 + (wid >> 2) * 2;
                g_cand[base] = p1;
                g_cand[base + 1] = p2;
            }
        }
    }
}

// ---------------------------------------------------------------------------
// Kernel 3: exact fp32 rerank. One warp per token over 256 candidates.
__global__ void __launch_bounds__(256)
rerank_kernel(const float* __restrict__ x, const float* __restrict__ cb) {
    const int wid = threadIdx.x >> 5;
    const int lane = threadIdx.x & 31;
    const int tok = blockIdx.x * 8 + wid;
    const unsigned long long* cand = g_cand + (size_t)tok * NCAND;

    unsigned long long v[8];
    unsigned long long mn = 0xFFFFFFFFFFFFFFFFull;
#pragma unroll
    for (int r = 0; r < 8; r++) {
        v[r] = cand[lane + 32 * r];
        if (v[r] < mn) mn = v[r];
    }
#pragma unroll
    for (int off = 16; off; off >>= 1) {
        unsigned long long o = __shfl_xor_sync(0xFFFFFFFFu, mn, off);
        if (o < mn) mn = o;
    }
    const float thr = unfkey((unsigned int)(mn >> 32)) + MARGIN;

    const int b = tok >> 10, hw = tok & 1023;
    const float* xt = x + (size_t)b * C_ * HW_ + hw;
    float xr[8];
#pragma unroll
    for (int q = 0; q < 8; q++)
        xr[q] = xt[(size_t)(lane + 32 * q) * HW_];

    float best_s = __uint_as_float(0x7F800000u);   // +inf
    unsigned int best_j = 0xFFFFFFFFu;
#pragma unroll 1
    for (int r = 0; r < 8; r++) {
        float sf = unfkey((unsigned int)(v[r] >> 32));
        unsigned int m = __ballot_sync(0xFFFFFFFFu, sf <= thr);
        while (m) {
            int src = __ffs(m) - 1;
            m &= m - 1;
            unsigned long long c = __shfl_sync(0xFFFFFFFFu, v[r], src);
            unsigned int j = (unsigned int)c;
            const float* row = cb + (size_t)j * C_;
            float dot = 0.0f;
#pragma unroll
            for (int q = 0; q < 8; q++)
                dot = fmaf(xr[q], row[lane + 32 * q], dot);
#pragma unroll
            for (int off = 16; off; off >>= 1)
                dot += __shfl_xor_sync(0xFFFFFFFFu, dot, off);
            float sc = fmaf(-2.0f, dot, g_cnorm[j]);
            if (sc < best_s || (sc == best_s && j < best_j)) {
                best_s = sc;
                best_j = j;
            }
        }
    }
    if (lane == 0) g_idx[tok] = best_j;
}

// ---------------------------------------------------------------------------
// Kernel 4: gather q, write qe + indices, per-block loss partials
__global__ void gather_kernel(const float* __restrict__ x,
                              const float* __restrict__ cb,
                              float* __restrict__ out) {
    const int bc = blockIdx.x;
    const int b = bc >> 8, c = bc & 255;
    const float* xrow = x + (size_t)bc * HW_;
    float* orow = out + (size_t)bc * HW_;
    float lsum = 0.0f;
#pragma unroll
    for (int r = 0; r < 4; r++) {
        int hw = threadIdx.x + r * 256;
        int n = b * HW_ + hw;
        unsigned int idx = g_idx[n];
        float q = cb[(size_t)idx * C_ + c];
        float dd = xrow[hw] - q;
        lsum += dd * dd;
        orow[hw] = q;
        if (c == 0) out[NQE + 1 + n] = (float)idx;
    }
    __shared__ float red[256];
    red[threadIdx.x] = lsum;
    __syncthreads();
#pragma unroll
    for (int s = 128; s; s >>= 1) {
        if (threadIdx.x < s) red[threadIdx.x] += red[threadIdx.x + s];
        __syncthreads();
    }
    if (threadIdx.x == 0) g_partial[bc] = red[0];
}

// Kernel 5: deterministic final loss reduction
__global__ void loss_kernel(float* __restrict__ out) {
    __shared__ float red[256];
    float s = 0.0f;
    for (int i = threadIdx.x; i < B_ * C_; i += 256) s += g_partial[i];
    red[threadIdx.x] = s;
    __syncthreads();
#pragma unroll
    for (int st = 128; st; st >>= 1) {
        if (threadIdx.x < st) red[threadIdx.x] += red[threadIdx.x + st];
        __syncthreads();
    }
    if (threadIdx.x == 0)
        out[NQE] = red[0] / (float)((size_t)N_ * C_);
}

// ---------------------------------------------------------------------------
extern "C" void kernel_launch(void* const* d_in, const int* in_sizes, int n_in,
                              void* d_out, int out_size) {
    const float* x  = (const float*)d_in[0];   // [16,256,32,32]
    const float* cb = (const float*)d_in[1];   // [8192,256]
    float* out = (float*)d_out;                // [qe | loss | indices]

    cudaFuncSetAttribute(argmin_mma_kernel,
                         cudaFuncAttributeMaxDynamicSharedMemorySize,
                         SMEM_BYTES);

    pconv_x_kernel<<<B_ * 64, 256>>>(x);
    pconv_cb_kernel<<<K_ / 8, 256>>>(cb);
    dim3 grid(N_ / TM, K_ / TN);
    argmin_mma_kernel<<<grid, 256, SMEM_BYTES>>>();
    rerank_kernel<<<N_ / 8, 256>>>(x, cb);
    gather_kernel<<<B_ * C_, 256>>>(x, cb, out);
    loss_kernel<<<1, 256>>>(out);
}

// round 13
// speedup vs baseline: 1.6587x; 1.6587x over previous
#include <cuda_runtime.h>
#include <cuda_fp16.h>
#include <cstdint>

// Problem constants
#define B_   16
#define C_   256
#define HW_  1024
#define K_   8192
#define N_   16384            // tokens
#define NQE  4194304          // qe elems

// Tiling
#define TM 128                 // tokens per CTA
#define TN 128                 // codes per CTA
#define KCH 32                 // K chunk (floats) = 16 k-pairs
#define NCHUNK (C_ / KCH)      // 8
#define NCAND 256              // candidates per token
#define MARGIN 3.5f            // rerank margin: fp16-accum noise + key truncation

// smem (uint32 units). A: [kp][t] stride 136; B: [nr][kp] stride 20. (R10 layout)
#define AST_A 136
#define A_U32 (16 * AST_A)             // 2176
#define BSTW 20
#define B_U32 (128 * BSTW)              // 2560
#define STAGE_U32 (A_U32 + B_U32)       // 4736
#define SMEM_BYTES (2 * STAGE_U32 * 4)  // 37888

// Scratch
__device__ uint32_t g_cand[(size_t)N_ * NCAND];             // 16MB packed keys
__device__ uint32_t g_xp[(size_t)B_ * 128 * HW_];           // 8MB  f16-pair x, [b][kp][t]
__device__ uint32_t g_cbp[(size_t)K_ * 128];                // 4MB  f16-pair cb, [n][kp]
__device__ unsigned int g_idx[N_];
__device__ float g_cnorm[K_];
__device__ float g_partial[B_ * C_];

__device__ __forceinline__ unsigned int fkey(float f) {
    unsigned int b = __float_as_uint(f);
    return (b & 0x80000000u) ? ~b : (b | 0x80000000u);
}
__device__ __forceinline__ float unfkey(unsigned int k) {
    unsigned int b = (k & 0x80000000u) ? (k & 0x7FFFFFFFu) : ~k;
    return __uint_as_float(b);
}
__device__ __forceinline__ uint32_t h_pair(float v0, float v1) {
    __half2 hp = __floats2half2_rn(v0, v1);
    return *(uint32_t*)&hp;
}
__device__ __forceinline__ uint32_t smem_u32(const void* p) {
    uint32_t a;
    asm("{ .reg .u64 t; cvta.to.shared.u64 t, %1; cvt.u32.u64 %0, t; }"
        : "=r"(a) : "l"(p));
    return a;
}
__device__ __forceinline__ void cp16(uint32_t dst, const void* src) {
    asm volatile("cp.async.cg.shared.global [%0], [%1], 16;"
                 :: "r"(dst), "l"(src));
}

// fp16-accumulate MMA: D (2x f16x2 regs) covers rows {g, g+8}, cols {2tg, 2tg+1}
#define MMA_F16ACC(D, A, B0, B1)                                            \
    asm volatile("mma.sync.aligned.m16n8k16.row.col.f16.f16.f16.f16 "       \
        "{%0,%1},{%2,%3,%4,%5},{%6,%7},{%0,%1};"                            \
        : "+r"((D)[0]), "+r"((D)[1])                                        \
        : "r"((A)[0]), "r"((A)[1]), "r"((A)[2]), "r"((A)[3]),               \
          "r"(B0), "r"(B1))

// ---------------------------------------------------------------------------
// Kernel 0a: preconvert x -> f16 pairs, layout [b][kp][t]  (R10 pconv)
__global__ void pconv_x_kernel(const float* __restrict__ x) {
    const int blk = blockIdx.x;              // b*128 + kp
    const int b = blk >> 7, kp = blk & 127;
    const float4* r0 = (const float4*)(x + ((size_t)(b * C_ + 2 * kp)) * HW_);
    const float4* r1 = (const float4*)(x + ((size_t)(b * C_ + 2 * kp + 1)) * HW_);
    const int t4 = threadIdx.x;              // 256 threads x 4 tokens
    float4 a = r0[t4], c = r1[t4];
    uint4 o;
    o.x = h_pair(a.x, c.x);
    o.y = h_pair(a.y, c.y);
    o.z = h_pair(a.z, c.z);
    o.w = h_pair(a.w, c.w);
    ((uint4*)(g_xp + (size_t)blk * HW_))[t4] = o;
}

// Kernel 0b: preconvert codebook -> f16 pairs [n][kp], fused with cnorm.
__global__ void pconv_cb_kernel(const float* __restrict__ cb) {
    int code = blockIdx.x * 8 + (threadIdx.x >> 5);
    int lane = threadIdx.x & 31;
    const float4* row = (const float4*)(cb + (size_t)code * C_);
    uint2* orow = (uint2*)(g_cbp + (size_t)code * 128);
    float s = 0.0f;
#pragma unroll
    for (int r = 0; r < 2; r++) {
        float4 v = row[lane + 32 * r];
        s += v.x * v.x + v.y * v.y + v.z * v.z + v.w * v.w;
        uint2 p;
        p.x = h_pair(v.x, v.y);
        p.y = h_pair(v.z, v.w);
        orow[lane + 32 * r] = p;
    }
#pragma unroll
    for (int off = 16; off; off >>= 1)
        s += __shfl_xor_sync(0xFFFFFFFFu, s, off);
    if (lane == 0) g_cnorm[code] = s;
}

// ---------------------------------------------------------------------------
// Kernel 2: fp16 screening GEMM (fp16 accum), cp.async loads, top-2 per
// n-warp per token, packed 32-bit candidates. grid=(128,64), block=256.
__global__ void __launch_bounds__(256, 2)
argmin_mma_kernel() {
    extern __shared__ uint32_t smemu[];
    __shared__ float cnS[TN];

    const int tid = threadIdx.x;
    const int wid = tid >> 5;
    const int lane = tid & 31;
    const int g  = lane >> 2;
    const int tg = lane & 3;
    const int m0w = (wid & 3) * 32;
    const int n0w = (wid >> 2) * 64;

    const int n0tok = blockIdx.x * TM;
    const int b   = n0tok >> 10;
    const int hw0 = n0tok & 1023;
    const int j0  = blockIdx.y * TN;

    if (tid < TN) cnS[tid] = g_cnorm[j0 + tid];

    const uint32_t sbase = smem_u32(smemu);
    const uint32_t* xpB = g_xp + (size_t)b * (128 * HW_) + hw0;  // + kp*HW_ + t

    uint32_t d[2][8][2];   // fp16x2 accumulators
#pragma unroll
    for (int i = 0; i < 2; i++)
#pragma unroll
        for (int j = 0; j < 8; j++) {
            d[i][j][0] = 0u; d[i][j][1] = 0u;
        }

    auto fill = [&](int k, int stg) {
        uint32_t As = sbase + (uint32_t)(stg * STAGE_U32 * 4);
        uint32_t Bs = As + A_U32 * 4;
#pragma unroll
        for (int r = 0; r < 2; r++) {
            int gi = tid + r * 256;
            int row = gi >> 5, c16 = gi & 31;
            cp16(As + (uint32_t)(row * (AST_A * 4) + c16 * 16),
                 xpB + (size_t)(k * 16 + row) * HW_ + c16 * 4);
        }
#pragma unroll
        for (int r = 0; r < 2; r++) {
            int gi = tid + r * 256;
            int nr = gi >> 2, c4 = gi & 3;
            cp16(Bs + (uint32_t)(nr * (BSTW * 4) + c4 * 16),
                 g_cbp + (size_t)(j0 + nr) * 128 + k * 16 + c4 * 4);
        }
        asm volatile("cp.async.commit_group;" ::: "memory");
    };

    auto mma_stage = [&](int stg) {
        const uint32_t* As = smemu + stg * STAGE_U32;
        const uint32_t* Bs = As + A_U32;
#pragma unroll
        for (int kk = 0; kk < 2; kk++) {
            const int kb = kk * 8 + tg;
            uint32_t ah[2][4];
#pragma unroll
            for (int dm = 0; dm < 2; dm++) {
                int mc = m0w + 16 * dm + g;
                ah[dm][0] = As[kb * AST_A + mc];
                ah[dm][1] = As[kb * AST_A + mc + 8];
                ah[dm][2] = As[(kb + 4) * AST_A + mc];
                ah[dm][3] = As[(kb + 4) * AST_A + mc + 8];
            }
#pragma unroll
            for (int dn = 0; dn < 8; dn++) {
                int nr = n0w + 8 * dn + g;
                uint32_t b0 = Bs[nr * BSTW + kb];
                uint32_t b1 = Bs[nr * BSTW + kb + 4];
                MMA_F16ACC(d[0][dn], ah[0], b0, b1);
                MMA_F16ACC(d[1][dn], ah[1], b0, b1);
            }
        }
    };

    fill(0, 0);
    fill(1, 1);
#pragma unroll 1
    for (int k = 0; k < NCHUNK; k++) {
        asm volatile("cp.async.wait_group 1;" ::: "memory");
        __syncthreads();
        mma_stage(k & 1);
        __syncthreads();
        if (k + 2 < NCHUNK) fill(k + 2, k & 1);
        else asm volatile("cp.async.commit_group;" ::: "memory");
    }

    // epilogue: per n-warp top-2 per token row; packed 32-bit keys
    // d[dm][dn][h] = f16x2 for (row = m0w+16dm+8h+g, cols 2tg, 2tg+1)
#pragma unroll
    for (int dm = 0; dm < 2; dm++) {
#pragma unroll
        for (int h = 0; h < 2; h++) {
            uint32_t p1 = 0xFFFFFFFFu, p2 = 0xFFFFFFFFu;
#pragma unroll
            for (int dn = 0; dn < 8; dn++) {
                __half2 hp = *(__half2*)&d[dm][dn][h];
                float2 dv = __half22float2(hp);
#pragma unroll
                for (int e = 0; e < 2; e++) {
                    int col = n0w + 8 * dn + 2 * tg + e;
                    float sc = fmaf(-2.0f, e ? dv.y : dv.x, cnS[col]);
                    uint32_t p = (fkey(sc) & 0xFFFFE000u) |
                                 (uint32_t)(j0 + col);
                    if (p < p1) { p2 = p1; p1 = p; }
                    else if (p < p2) { p2 = p; }
                }
            }
#pragma unroll
            for (int off = 1; off <= 2; off <<= 1) {
                uint32_t q1 = __shfl_xor_sync(0xFFFFFFFFu, p1, off);
                uint32_t q2 = __shfl_xor_sync(0xFFFFFFFFu, p2, off);
                if (q1 < p1) { p2 = (p1 < q2) ? p1 : q2; p1 = q1; }
                else         { p2 = (p2 < q1) ? p2 : q1; }
            }
            if (tg == 0) {
                int tok = n0tok + m0w + 16 * dm + 8 * h + g;
                size_t base = (size_t)tok * NCAND + blockIdx.y * 4 + (wid >> 2) * 2;
                g_cand[base] = p1;
                g_cand[base + 1] = p2;
            }
        }
    }
}

// ---------------------------------------------------------------------------
// Kernel 3: exact fp32 rerank. One warp per token over 256 packed candidates.
__global__ void __launch_bounds__(256)
rerank_kernel(const float* __restrict__ x, const float* __restrict__ cb) {
    const int wid = threadIdx.x >> 5;
    const int lane = threadIdx.x & 31;
    const int tok = blockIdx.x * 8 + wid;
    const uint32_t* cand = g_cand + (size_t)tok * NCAND;

    uint32_t v[8];
    uint32_t mn = 0xFFFFFFFFu;
#pragma unroll
    for (int r = 0; r < 8; r++) {
        v[r] = cand[lane + 32 * r];
        if (v[r] < mn) mn = v[r];
    }
#pragma unroll
    for (int off = 16; off; off >>= 1) {
        uint32_t o = __shfl_xor_sync(0xFFFFFFFFu, mn, off);
        if (o < mn) mn = o;
    }
    // min's score upper bound + margin; candidates tested on lower bound
    const float thr = unfkey(mn | 0x1FFFu) + MARGIN;

    const int b = tok >> 10, hw = tok & 1023;
    const float* xt = x + (size_t)b * C_ * HW_ + hw;
    float xr[8];
#pragma unroll
    for (int q = 0; q < 8; q++)
        xr[q] = xt[(size_t)(lane + 32 * q) * HW_];

    float best_s = __uint_as_float(0x7F800000u);   // +inf
    unsigned int best_j = 0xFFFFFFFFu;
#pragma unroll 1
    for (int r = 0; r < 8; r++) {
        float sf = unfkey(v[r] & 0xFFFFE000u);
        unsigned int m = __ballot_sync(0xFFFFFFFFu, sf <= thr);
        while (m) {
            int src = __ffs(m) - 1;
            m &= m - 1;
            uint32_t c = __shfl_sync(0xFFFFFFFFu, v[r], src);
            unsigned int j = c & 0x1FFFu;
            const float* row = cb + (size_t)j * C_;
            float dot = 0.0f;
#pragma unroll
            for (int q = 0; q < 8; q++)
                dot = fmaf(xr[q], row[lane + 32 * q], dot);
#pragma unroll
            for (int off = 16; off; off >>= 1)
                dot += __shfl_xor_sync(0xFFFFFFFFu, dot, off);
            float sc = fmaf(-2.0f, dot, g_cnorm[j]);
            if (sc < best_s || (sc == best_s && j < best_j)) {
                best_s = sc;
                best_j = j;
            }
        }
    }
    if (lane == 0) g_idx[tok] = best_j;
}

// ---------------------------------------------------------------------------
// Kernel 4: gather q, write qe + indices, per-block loss partials
__global__ void gather_kernel(const float* __restrict__ x,
                              const float* __restrict__ cb,
                              float* __restrict__ out) {
    const int bc = blockIdx.x;
    const int b = bc >> 8, c = bc & 255;
    const float* xrow = x + (size_t)bc * HW_;
    float* orow = out + (size_t)bc * HW_;
    float lsum = 0.0f;
#pragma unroll
    for (int r = 0; r < 4; r++) {
        int hw = threadIdx.x + r * 256;
        int n = b * HW_ + hw;
        unsigned int idx = g_idx[n];
        float q = cb[(size_t)idx * C_ + c];
        float dd = xrow[hw] - q;
        lsum += dd * dd;
        orow[hw] = q;
        if (c == 0) out[NQE + 1 + n] = (float)idx;
    }
    __shared__ float red[256];
    red[threadIdx.x] = lsum;
    __syncthreads();
#pragma unroll
    for (int s = 128; s; s >>= 1) {
        if (threadIdx.x < s) red[threadIdx.x] += red[threadIdx.x + s];
        __syncthreads();
    }
    if (threadIdx.x == 0) g_partial[bc] = red[0];
}

// Kernel 5: deterministic final loss reduction
__global__ void loss_kernel(float* __restrict__ out) {
    __shared__ float red[256];
    float s = 0.0f;
    for (int i = threadIdx.x; i < B_ * C_; i += 256) s += g_partial[i];
    red[threadIdx.x] = s;
    __syncthreads();
#pragma unroll
    for (int st = 128; st; st >>= 1) {
        if (threadIdx.x < st) red[threadIdx.x] += red[threadIdx.x + st];
        __syncthreads();
    }
    if (threadIdx.x == 0)
        out[NQE] = red[0] / (float)((size_t)N_ * C_);
}

// ---------------------------------------------------------------------------
extern "C" void kernel_launch(void* const* d_in, const int* in_sizes, int n_in,
                              void* d_out, int out_size) {
    const float* x  = (const float*)d_in[0];   // [16,256,32,32]
    const float* cb = (const float*)d_in[1];   // [8192,256]
    float* out = (float*)d_out;                // [qe | loss | indices]

    cudaFuncSetAttribute(argmin_mma_kernel,
                         cudaFuncAttributeMaxDynamicSharedMemorySize,
                         SMEM_BYTES);

    pconv_x_kernel<<<B_ * 128, 256>>>(x);
    pconv_cb_kernel<<<K_ / 8, 256>>>(cb);
    dim3 grid(N_ / TM, K_ / TN);
    argmin_mma_kernel<<<grid, 256, SMEM_BYTES>>>();
    rerank_kernel<<<N_ / 8, 256>>>(x, cb);
    gather_kernel<<<B_ * C_, 256>>>(x, cb, out);
    loss_kernel<<<1, 256>>>(out);
}

// round 14
// speedup vs baseline: 1.7564x; 1.0589x over previous
#include <cuda_runtime.h>
#include <cuda_fp16.h>
#include <cstdint>

// Problem constants
#define B_   16
#define C_   256
#define HW_  1024
#define K_   8192
#define N_   16384            // tokens
#define NQE  4194304          // qe elems

// Tiling
#define TM 128                 // tokens per CTA
#define TN 128                 // codes per CTA
#define KCH 32                 // K chunk (floats) = 16 k-pairs
#define NCHUNK (C_ / KCH)      // 8
#define NCAND 256              // candidates per token
#define MARGIN 3.5f            // rerank margin: fp16-accum noise + key truncation

// smem (uint32 units). A: [kp][t] stride 136; B: [nr][kp] stride 20.
#define AST_A 136
#define A_U32 (16 * AST_A)             // 2176
#define BSTW 20
#define B_U32 (128 * BSTW)              // 2560
#define STAGE_U32 (A_U32 + B_U32)       // 4736
#define SMEM_BYTES (2 * STAGE_U32 * 4)  // 37888

// Scratch
__device__ uint32_t g_cand[(size_t)N_ * NCAND];             // 16MB packed keys
__device__ uint32_t g_xp[(size_t)B_ * 128 * HW_];           // 8MB  f16-pair x, [b][kp][t]
__device__ uint32_t g_cbp[(size_t)K_ * 128];                // 4MB  f16-pair cb, [n][kp]
__device__ float g_xt[(size_t)B_ * HW_ * C_];               // 16MB fp32 x, [b][hw][c]
__device__ unsigned int g_idx[N_];
__device__ float g_cnorm[K_];
__device__ float g_partial[N_ / 32];

__device__ __forceinline__ unsigned int fkey(float f) {
    unsigned int b = __float_as_uint(f);
    return (b & 0x80000000u) ? ~b : (b | 0x80000000u);
}
__device__ __forceinline__ float unfkey(unsigned int k) {
    unsigned int b = (k & 0x80000000u) ? (k & 0x7FFFFFFFu) : ~k;
    return __uint_as_float(b);
}
__device__ __forceinline__ uint32_t h_pair(float v0, float v1) {
    __half2 hp = __floats2half2_rn(v0, v1);
    return *(uint32_t*)&hp;
}
__device__ __forceinline__ uint32_t smem_u32(const void* p) {
    uint32_t a;
    asm("{ .reg .u64 t; cvta.to.shared.u64 t, %1; cvt.u32.u64 %0, t; }"
        : "=r"(a) : "l"(p));
    return a;
}
__device__ __forceinline__ void cp16(uint32_t dst, const void* src) {
    asm volatile("cp.async.cg.shared.global [%0], [%1], 16;"
                 :: "r"(dst), "l"(src));
}

#define MMA_F16ACC(D, A, B0, B1)                                            \
    asm volatile("mma.sync.aligned.m16n8k16.row.col.f16.f16.f16.f16 "       \
        "{%0,%1},{%2,%3,%4,%5},{%6,%7},{%0,%1};"                            \
        : "+r"((D)[0]), "+r"((D)[1])                                        \
        : "r"((A)[0]), "r"((A)[1]), "r"((A)[2]), "r"((A)[3]),               \
          "r"(B0), "r"(B1))

// ---------------------------------------------------------------------------
// Kernel 0a: preconvert x -> f16 pairs, layout [b][kp][t]
__global__ void pconv_x_kernel(const float* __restrict__ x) {
    const int blk = blockIdx.x;              // b*128 + kp
    const int b = blk >> 7, kp = blk & 127;
    const float4* r0 = (const float4*)(x + ((size_t)(b * C_ + 2 * kp)) * HW_);
    const float4* r1 = (const float4*)(x + ((size_t)(b * C_ + 2 * kp + 1)) * HW_);
    const int t4 = threadIdx.x;
    float4 a = r0[t4], c = r1[t4];
    uint4 o;
    o.x = h_pair(a.x, c.x);
    o.y = h_pair(a.y, c.y);
    o.z = h_pair(a.z, c.z);
    o.w = h_pair(a.w, c.w);
    ((uint4*)(g_xp + (size_t)blk * HW_))[t4] = o;
}

// Kernel 0b: preconvert codebook -> f16 pairs [n][kp], fused with cnorm.
__global__ void pconv_cb_kernel(const float* __restrict__ cb) {
    int code = blockIdx.x * 8 + (threadIdx.x >> 5);
    int lane = threadIdx.x & 31;
    const float4* row = (const float4*)(cb + (size_t)code * C_);
    uint2* orow = (uint2*)(g_cbp + (size_t)code * 128);
    float s = 0.0f;
#pragma unroll
    for (int r = 0; r < 2; r++) {
        float4 v = row[lane + 32 * r];
        s += v.x * v.x + v.y * v.y + v.z * v.z + v.w * v.w;
        uint2 p;
        p.x = h_pair(v.x, v.y);
        p.y = h_pair(v.z, v.w);
        orow[lane + 32 * r] = p;
    }
#pragma unroll
    for (int off = 16; off; off >>= 1)
        s += __shfl_xor_sync(0xFFFFFFFFu, s, off);
    if (lane == 0) g_cnorm[code] = s;
}

// Kernel 0c: transpose x -> fp32 [b][hw][c] (coalesced both sides).
__global__ void pconv_xt_kernel(const float* __restrict__ x) {
    __shared__ float sm[32][33];
    const int bx = blockIdx.x;               // b*256 + ct*32 + hwt
    const int b = bx >> 8;
    const int c0 = ((bx >> 5) & 7) * 32;
    const int hw0 = (bx & 31) * 32;
    const int tid = threadIdx.x;
    const int i = tid >> 5, j = tid & 31;
#pragma unroll
    for (int r = 0; r < 4; r++) {
        int row = i + 8 * r;                  // channel within tile
        sm[row][j] = x[((size_t)(b * C_ + c0 + row)) * HW_ + hw0 + j];
    }
    __syncthreads();
#pragma unroll
    for (int r = 0; r < 4; r++) {
        int row = i + 8 * r;                  // hw within tile
        g_xt[((size_t)(b * HW_ + hw0 + row)) * C_ + c0 + j] = sm[j][row];
    }
}

// ---------------------------------------------------------------------------
// Kernel 2: fp16 screening GEMM (fp16 accum), cp.async loads, top-2 per
// n-warp per token, packed 32-bit candidates. grid=(128,64), block=256.
__global__ void __launch_bounds__(256, 2)
argmin_mma_kernel() {
    extern __shared__ uint32_t smemu[];
    __shared__ float cnS[TN];

    const int tid = threadIdx.x;
    const int wid = tid >> 5;
    const int lane = tid & 31;
    const int g  = lane >> 2;
    const int tg = lane & 3;
    const int m0w = (wid & 3) * 32;
    const int n0w = (wid >> 2) * 64;

    const int n0tok = blockIdx.x * TM;
    const int b   = n0tok >> 10;
    const int hw0 = n0tok & 1023;
    const int j0  = blockIdx.y * TN;

    if (tid < TN) cnS[tid] = g_cnorm[j0 + tid];

    const uint32_t sbase = smem_u32(smemu);
    const uint32_t* xpB = g_xp + (size_t)b * (128 * HW_) + hw0;

    uint32_t d[2][8][2];
#pragma unroll
    for (int i = 0; i < 2; i++)
#pragma unroll
        for (int j = 0; j < 8; j++) {
            d[i][j][0] = 0u; d[i][j][1] = 0u;
        }

    auto fill = [&](int k, int stg) {
        uint32_t As = sbase + (uint32_t)(stg * STAGE_U32 * 4);
        uint32_t Bs = As + A_U32 * 4;
#pragma unroll
        for (int r = 0; r < 2; r++) {
            int gi = tid + r * 256;
            int row = gi >> 5, c16 = gi & 31;
            cp16(As + (uint32_t)(row * (AST_A * 4) + c16 * 16),
                 xpB + (size_t)(k * 16 + row) * HW_ + c16 * 4);
        }
#pragma unroll
        for (int r = 0; r < 2; r++) {
            int gi = tid + r * 256;
            int nr = gi >> 2, c4 = gi & 3;
            cp16(Bs + (uint32_t)(nr * (BSTW * 4) + c4 * 16),
                 g_cbp + (size_t)(j0 + nr) * 128 + k * 16 + c4 * 4);
        }
        asm volatile("cp.async.commit_group;" ::: "memory");
    };

    auto mma_stage = [&](int stg) {
        const uint32_t* As = smemu + stg * STAGE_U32;
        const uint32_t* Bs = As + A_U32;
#pragma unroll
        for (int kk = 0; kk < 2; kk++) {
            const int kb = kk * 8 + tg;
            uint32_t ah[2][4];
#pragma unroll
            for (int dm = 0; dm < 2; dm++) {
                int mc = m0w + 16 * dm + g;
                ah[dm][0] = As[kb * AST_A + mc];
                ah[dm][1] = As[kb * AST_A + mc + 8];
                ah[dm][2] = As[(kb + 4) * AST_A + mc];
                ah[dm][3] = As[(kb + 4) * AST_A + mc + 8];
            }
#pragma unroll
            for (int dn = 0; dn < 8; dn++) {
                int nr = n0w + 8 * dn + g;
                uint32_t b0 = Bs[nr * BSTW + kb];
                uint32_t b1 = Bs[nr * BSTW + kb + 4];
                MMA_F16ACC(d[0][dn], ah[0], b0, b1);
                MMA_F16ACC(d[1][dn], ah[1], b0, b1);
            }
        }
    };

    fill(0, 0);
    fill(1, 1);
#pragma unroll 1
    for (int k = 0; k < NCHUNK; k++) {
        asm volatile("cp.async.wait_group 1;" ::: "memory");
        __syncthreads();
        mma_stage(k & 1);
        __syncthreads();
        if (k + 2 < NCHUNK) fill(k + 2, k & 1);
        else asm volatile("cp.async.commit_group;" ::: "memory");
    }

    // epilogue: per n-warp top-2 per token row; packed 32-bit keys
#pragma unroll
    for (int dm = 0; dm < 2; dm++) {
#pragma unroll
        for (int h = 0; h < 2; h++) {
            uint32_t p1 = 0xFFFFFFFFu, p2 = 0xFFFFFFFFu;
#pragma unroll
            for (int dn = 0; dn < 8; dn++) {
                __half2 hp = *(__half2*)&d[dm][dn][h];
                float2 dv = __half22float2(hp);
#pragma unroll
                for (int e = 0; e < 2; e++) {
                    int col = n0w + 8 * dn + 2 * tg + e;
                    float sc = fmaf(-2.0f, e ? dv.y : dv.x, cnS[col]);
                    uint32_t p = (fkey(sc) & 0xFFFFE000u) |
                                 (uint32_t)(j0 + col);
                    if (p < p1) { p2 = p1; p1 = p; }
                    else if (p < p2) { p2 = p; }
                }
            }
#pragma unroll
            for (int off = 1; off <= 2; off <<= 1) {
                uint32_t q1 = __shfl_xor_sync(0xFFFFFFFFu, p1, off);
                uint32_t q2 = __shfl_xor_sync(0xFFFFFFFFu, p2, off);
                if (q1 < p1) { p2 = (p1 < q2) ? p1 : q2; p1 = q1; }
                else         { p2 = (p2 < q1) ? p2 : q1; }
            }
            if (tg == 0) {
                int tok = n0tok + m0w + 16 * dm + 8 * h + g;
                size_t base = (size_t)tok * NCAND + blockIdx.y * 4 + (wid >> 2) * 2;
                g_cand[base] = p1;
                g_cand[base + 1] = p2;
            }
        }
    }
}

// ---------------------------------------------------------------------------
// Kernel 3: exact fp32 rerank. One warp per token; coalesced x via g_xt.
__global__ void __launch_bounds__(256)
rerank_kernel(const float* __restrict__ cb) {
    const int wid = threadIdx.x >> 5;
    const int lane = threadIdx.x & 31;
    const int tok = blockIdx.x * 8 + wid;
    const uint32_t* cand = g_cand + (size_t)tok * NCAND;

    uint32_t v[8];
    uint32_t mn = 0xFFFFFFFFu;
#pragma unroll
    for (int r = 0; r < 8; r++) {
        v[r] = cand[lane + 32 * r];
        if (v[r] < mn) mn = v[r];
    }
#pragma unroll
    for (int off = 16; off; off >>= 1) {
        uint32_t o = __shfl_xor_sync(0xFFFFFFFFu, mn, off);
        if (o < mn) mn = o;
    }
    const float thr = unfkey(mn | 0x1FFFu) + MARGIN;

    const float* xt = g_xt + (size_t)tok * C_;
    float xr[8];
#pragma unroll
    for (int q = 0; q < 8; q++)
        xr[q] = xt[lane + 32 * q];             // coalesced

    float best_s = __uint_as_float(0x7F800000u);
    unsigned int best_j = 0xFFFFFFFFu;
#pragma unroll 1
    for (int r = 0; r < 8; r++) {
        float sf = unfkey(v[r] & 0xFFFFE000u);
        unsigned int m = __ballot_sync(0xFFFFFFFFu, sf <= thr);
        while (m) {
            int src = __ffs(m) - 1;
            m &= m - 1;
            uint32_t c = __shfl_sync(0xFFFFFFFFu, v[r], src);
            unsigned int j = c & 0x1FFFu;
            const float* row = cb + (size_t)j * C_;
            float dot = 0.0f;
#pragma unroll
            for (int q = 0; q < 8; q++)
                dot = fmaf(xr[q], row[lane + 32 * q], dot);
#pragma unroll
            for (int off = 16; off; off >>= 1)
                dot += __shfl_xor_sync(0xFFFFFFFFu, dot, off);
            float sc = fmaf(-2.0f, dot, g_cnorm[j]);
            if (sc < best_s || (sc == best_s && j < best_j)) {
                best_s = sc;
                best_j = j;
            }
        }
    }
    if (lane == 0) g_idx[tok] = best_j;
}

// ---------------------------------------------------------------------------
// Kernel 4: gather. One block per 32 tokens; staged codebook rows in smem;
// all gmem traffic coalesced. grid = N/32 = 512, block 256 (8 warps).
__global__ void gather_kernel(const float* __restrict__ x,
                              const float* __restrict__ cb,
                              float* __restrict__ out) {
    __shared__ float qs[32][257];
    __shared__ float red[256];
    const int blk = blockIdx.x;
    const int tok0 = blk * 32;
    const int b = tok0 >> 10, hw0 = tok0 & 1023;
    const int tid = threadIdx.x;
    const int wid = tid >> 5, lane = tid & 31;

    // phase 1: stage 32 gathered codebook rows (each 1KB, coalesced)
#pragma unroll 1
    for (int r = 0; r < 32; r++) {
        unsigned int idx = g_idx[tok0 + r];
        qs[r][tid] = cb[(size_t)idx * C_ + tid];
    }
    // indices output
    if (tid < 32) out[NQE + 1 + tok0 + tid] = (float)g_idx[tok0 + tid];
    __syncthreads();

    // phase 2: each warp owns 32 channels; lane = token (coalesced x/qe)
    float lsum = 0.0f;
#pragma unroll
    for (int i = 0; i < 32; i++) {
        int c = wid * 32 + i;
        float q = qs[lane][c];
        size_t off = ((size_t)(b * C_ + c)) * HW_ + hw0 + lane;
        float dd = x[off] - q;
        lsum += dd * dd;
        out[off] = q;
    }
    red[tid] = lsum;
    __syncthreads();
#pragma unroll
    for (int s = 128; s; s >>= 1) {
        if (tid < s) red[tid] += red[tid + s];
        __syncthreads();
    }
    if (tid == 0) g_partial[blk] = red[0];
}

// Kernel 5: deterministic final loss reduction (512 partials)
__global__ void loss_kernel(float* __restrict__ out) {
    __shared__ float red[256];
    float s = 0.0f;
    for (int i = threadIdx.x; i < N_ / 32; i += 256) s += g_partial[i];
    red[threadIdx.x] = s;
    __syncthreads();
#pragma unroll
    for (int st = 128; st; st >>= 1) {
        if (threadIdx.x < st) red[threadIdx.x] += red[threadIdx.x + st];
        __syncthreads();
    }
    if (threadIdx.x == 0)
        out[NQE] = red[0] / (float)((size_t)N_ * C_);
}

// ---------------------------------------------------------------------------
extern "C" void kernel_launch(void* const* d_in, const int* in_sizes, int n_in,
                              void* d_out, int out_size) {
    const float* x  = (const float*)d_in[0];   // [16,256,32,32]
    const float* cb = (const float*)d_in[1];   // [8192,256]
    float* out = (float*)d_out;                // [qe | loss | indices]

    cudaFuncSetAttribute(argmin_mma_kernel,
                         cudaFuncAttributeMaxDynamicSharedMemorySize,
                         SMEM_BYTES);

    pconv_x_kernel<<<B_ * 128, 256>>>(x);
    pconv_cb_kernel<<<K_ / 8, 256>>>(cb);
    pconv_xt_kernel<<<B_ * 256, 256>>>(x);
    dim3 grid(N_ / TM, K_ / TN);
    argmin_mma_kernel<<<grid, 256, SMEM_BYTES>>>();
    rerank_kernel<<<N_ / 8, 256>>>(cb);
    gather_kernel<<<N_ / 32, 256>>>(x, cb, out);
    loss_kernel<<<1, 256>>>(out);
}

// round 15
// speedup vs baseline: 1.8729x; 1.0664x over previous
#include <cuda_runtime.h>
#include <cuda_fp16.h>
#include <cstdint>

// Problem constants
#define B_   16
#define C_   256
#define HW_  1024
#define K_   8192
#define N_   16384            // tokens
#define NQE  4194304          // qe elems

// Tiling
#define TM 128                 // tokens per CTA
#define TN 128                 // codes per CTA
#define KCH 32                 // K chunk (floats) = 16 k-pairs
#define NCHUNK (C_ / KCH)      // 8
#define NCAND 256              // candidates per token
#define MARGIN 3.5f            // rerank margin: fp16-accum noise + key truncation
#define NSTAGE 3

// smem (uint32 units). A: [kp][t] stride 136; B: [nr][kp] stride 20.
#define AST_A 136
#define A_U32 (16 * AST_A)             // 2176
#define BSTW 20
#define B_U32 (128 * BSTW)              // 2560
#define STAGE_U32 (A_U32 + B_U32)       // 4736
#define SMEM_BYTES (NSTAGE * STAGE_U32 * 4)  // 56832

// Scratch
__device__ uint32_t g_cand[(size_t)N_ * NCAND];             // 16MB packed keys
__device__ uint32_t g_xp[(size_t)B_ * 128 * HW_];           // 8MB  f16-pair x, [b][kp][t]
__device__ uint32_t g_cbp[(size_t)K_ * 128];                // 4MB  f16-pair cb, [n][kp]
__device__ float g_xt[(size_t)B_ * HW_ * C_];               // 16MB fp32 x, [b][hw][c]
__device__ unsigned int g_idx[N_];
__device__ float g_cnorm[K_];
__device__ float g_partial[N_ / 32];

__device__ __forceinline__ unsigned int fkey(float f) {
    unsigned int b = __float_as_uint(f);
    return (b & 0x80000000u) ? ~b : (b | 0x80000000u);
}
__device__ __forceinline__ float unfkey(unsigned int k) {
    unsigned int b = (k & 0x80000000u) ? (k & 0x7FFFFFFFu) : ~k;
    return __uint_as_float(b);
}
__device__ __forceinline__ uint32_t h_pair(float v0, float v1) {
    __half2 hp = __floats2half2_rn(v0, v1);
    return *(uint32_t*)&hp;
}
__device__ __forceinline__ uint32_t smem_u32(const void* p) {
    uint32_t a;
    asm("{ .reg .u64 t; cvta.to.shared.u64 t, %1; cvt.u32.u64 %0, t; }"
        : "=r"(a) : "l"(p));
    return a;
}
__device__ __forceinline__ void cp16(uint32_t dst, const void* src) {
    asm volatile("cp.async.cg.shared.global [%0], [%1], 16;"
                 :: "r"(dst), "l"(src));
}

#define MMA_F16ACC(D, A, B0, B1)                                            \
    asm volatile("mma.sync.aligned.m16n8k16.row.col.f16.f16.f16.f16 "       \
        "{%0,%1},{%2,%3,%4,%5},{%6,%7},{%0,%1};"                            \
        : "+r"((D)[0]), "+r"((D)[1])                                        \
        : "r"((A)[0]), "r"((A)[1]), "r"((A)[2]), "r"((A)[3]),               \
          "r"(B0), "r"(B1))

// ---------------------------------------------------------------------------
// Kernel 0a: preconvert x -> f16 pairs, layout [b][kp][t]
__global__ void pconv_x_kernel(const float* __restrict__ x) {
    const int blk = blockIdx.x;              // b*128 + kp
    const int b = blk >> 7, kp = blk & 127;
    const float4* r0 = (const float4*)(x + ((size_t)(b * C_ + 2 * kp)) * HW_);
    const float4* r1 = (const float4*)(x + ((size_t)(b * C_ + 2 * kp + 1)) * HW_);
    const int t4 = threadIdx.x;
    float4 a = r0[t4], c = r1[t4];
    uint4 o;
    o.x = h_pair(a.x, c.x);
    o.y = h_pair(a.y, c.y);
    o.z = h_pair(a.z, c.z);
    o.w = h_pair(a.w, c.w);
    ((uint4*)(g_xp + (size_t)blk * HW_))[t4] = o;
}

// Kernel 0b: preconvert codebook -> f16 pairs [n][kp], fused with cnorm.
__global__ void pconv_cb_kernel(const float* __restrict__ cb) {
    int code = blockIdx.x * 8 + (threadIdx.x >> 5);
    int lane = threadIdx.x & 31;
    const float4* row = (const float4*)(cb + (size_t)code * C_);
    uint2* orow = (uint2*)(g_cbp + (size_t)code * 128);
    float s = 0.0f;
#pragma unroll
    for (int r = 0; r < 2; r++) {
        float4 v = row[lane + 32 * r];
        s += v.x * v.x + v.y * v.y + v.z * v.z + v.w * v.w;
        uint2 p;
        p.x = h_pair(v.x, v.y);
        p.y = h_pair(v.z, v.w);
        orow[lane + 32 * r] = p;
    }
#pragma unroll
    for (int off = 16; off; off >>= 1)
        s += __shfl_xor_sync(0xFFFFFFFFu, s, off);
    if (lane == 0) g_cnorm[code] = s;
}

// Kernel 0c: transpose x -> fp32 [b][hw][c] (coalesced both sides).
__global__ void pconv_xt_kernel(const float* __restrict__ x) {
    __shared__ float sm[32][33];
    const int bx = blockIdx.x;
    const int b = bx >> 8;
    const int c0 = ((bx >> 5) & 7) * 32;
    const int hw0 = (bx & 31) * 32;
    const int tid = threadIdx.x;
    const int i = tid >> 5, j = tid & 31;
#pragma unroll
    for (int r = 0; r < 4; r++) {
        int row = i + 8 * r;
        sm[row][j] = x[((size_t)(b * C_ + c0 + row)) * HW_ + hw0 + j];
    }
    __syncthreads();
#pragma unroll
    for (int r = 0; r < 4; r++) {
        int row = i + 8 * r;
        g_xt[((size_t)(b * HW_ + hw0 + row)) * C_ + c0 + j] = sm[j][row];
    }
}

// ---------------------------------------------------------------------------
// Kernel 2: fp16 screening GEMM (fp16 accum), 3-stage cp.async pipeline,
// 3 CTAs/SM, top-2 per n-warp per token. grid=(128,64), block=256.
__global__ void __launch_bounds__(256, 3)
argmin_mma_kernel() {
    extern __shared__ uint32_t smemu[];
    __shared__ float cnS[TN];

    const int tid = threadIdx.x;
    const int wid = tid >> 5;
    const int lane = tid & 31;
    const int g  = lane >> 2;
    const int tg = lane & 3;
    const int m0w = (wid & 3) * 32;
    const int n0w = (wid >> 2) * 64;

    const int n0tok = blockIdx.x * TM;
    const int b   = n0tok >> 10;
    const int hw0 = n0tok & 1023;
    const int j0  = blockIdx.y * TN;

    if (tid < TN) cnS[tid] = g_cnorm[j0 + tid];

    const uint32_t sbase = smem_u32(smemu);
    const uint32_t* xpB = g_xp + (size_t)b * (128 * HW_) + hw0;

    uint32_t d[2][8][2];
#pragma unroll
    for (int i = 0; i < 2; i++)
#pragma unroll
        for (int j = 0; j < 8; j++) {
            d[i][j][0] = 0u; d[i][j][1] = 0u;
        }

    auto fill = [&](int k, int stg) {
        uint32_t As = sbase + (uint32_t)(stg * STAGE_U32 * 4);
        uint32_t Bs = As + A_U32 * 4;
#pragma unroll
        for (int r = 0; r < 2; r++) {
            int gi = tid + r * 256;
            int row = gi >> 5, c16 = gi & 31;
            cp16(As + (uint32_t)(row * (AST_A * 4) + c16 * 16),
                 xpB + (size_t)(k * 16 + row) * HW_ + c16 * 4);
        }
#pragma unroll
        for (int r = 0; r < 2; r++) {
            int gi = tid + r * 256;
            int nr = gi >> 2, c4 = gi & 3;
            cp16(Bs + (uint32_t)(nr * (BSTW * 4) + c4 * 16),
                 g_cbp + (size_t)(j0 + nr) * 128 + k * 16 + c4 * 4);
        }
        asm volatile("cp.async.commit_group;" ::: "memory");
    };

    auto mma_stage = [&](int stg) {
        const uint32_t* As = smemu + stg * STAGE_U32;
        const uint32_t* Bs = As + A_U32;
#pragma unroll
        for (int kk = 0; kk < 2; kk++) {
            const int kb = kk * 8 + tg;
            uint32_t ah[2][4];
#pragma unroll
            for (int dm = 0; dm < 2; dm++) {
                int mc = m0w + 16 * dm + g;
                ah[dm][0] = As[kb * AST_A + mc];
                ah[dm][1] = As[kb * AST_A + mc + 8];
                ah[dm][2] = As[(kb + 4) * AST_A + mc];
                ah[dm][3] = As[(kb + 4) * AST_A + mc + 8];
            }
#pragma unroll
            for (int dn = 0; dn < 8; dn++) {
                int nr = n0w + 8 * dn + g;
                uint32_t b0 = Bs[nr * BSTW + kb];
                uint32_t b1 = Bs[nr * BSTW + kb + 4];
                MMA_F16ACC(d[0][dn], ah[0], b0, b1);
                MMA_F16ACC(d[1][dn], ah[1], b0, b1);
            }
        }
    };

    fill(0, 0);
    fill(1, 1);
    fill(2, 2);
#pragma unroll 1
    for (int k = 0; k < NCHUNK; k++) {
        asm volatile("cp.async.wait_group 2;" ::: "memory");
        __syncthreads();
        mma_stage(k % NSTAGE);
        __syncthreads();
        if (k + NSTAGE < NCHUNK) fill(k + NSTAGE, k % NSTAGE);
        else asm volatile("cp.async.commit_group;" ::: "memory");
    }

    // epilogue: per n-warp top-2 per token row; packed 32-bit keys
#pragma unroll
    for (int dm = 0; dm < 2; dm++) {
#pragma unroll
        for (int h = 0; h < 2; h++) {
            uint32_t p1 = 0xFFFFFFFFu, p2 = 0xFFFFFFFFu;
#pragma unroll
            for (int dn = 0; dn < 8; dn++) {
                __half2 hp = *(__half2*)&d[dm][dn][h];
                float2 dv = __half22float2(hp);
#pragma unroll
                for (int e = 0; e < 2; e++) {
                    int col = n0w + 8 * dn + 2 * tg + e;
                    float sc = fmaf(-2.0f, e ? dv.y : dv.x, cnS[col]);
                    uint32_t p = (fkey(sc) & 0xFFFFE000u) |
                                 (uint32_t)(j0 + col);
                    if (p < p1) { p2 = p1; p1 = p; }
                    else if (p < p2) { p2 = p; }
                }
            }
#pragma unroll
            for (int off = 1; off <= 2; off <<= 1) {
                uint32_t q1 = __shfl_xor_sync(0xFFFFFFFFu, p1, off);
                uint32_t q2 = __shfl_xor_sync(0xFFFFFFFFu, p2, off);
                if (q1 < p1) { p2 = (p1 < q2) ? p1 : q2; p1 = q1; }
                else         { p2 = (p2 < q1) ? p2 : q1; }
            }
            if (tg == 0) {
                int tok = n0tok + m0w + 16 * dm + 8 * h + g;
                size_t base = (size_t)tok * NCAND + blockIdx.y * 4 + (wid >> 2) * 2;
                g_cand[base] = p1;
                g_cand[base + 1] = p2;
            }
        }
    }
}

// ---------------------------------------------------------------------------
// Kernel 3: exact fp32 rerank. One warp per token; coalesced x via g_xt.
__global__ void __launch_bounds__(256)
rerank_kernel(const float* __restrict__ cb) {
    const int wid = threadIdx.x >> 5;
    const int lane = threadIdx.x & 31;
    const int tok = blockIdx.x * 8 + wid;
    const uint32_t* cand = g_cand + (size_t)tok * NCAND;

    uint32_t v[8];
    uint32_t mn = 0xFFFFFFFFu;
#pragma unroll
    for (int r = 0; r < 8; r++) {
        v[r] = cand[lane + 32 * r];
        if (v[r] < mn) mn = v[r];
    }
#pragma unroll
    for (int off = 16; off; off >>= 1) {
        uint32_t o = __shfl_xor_sync(0xFFFFFFFFu, mn, off);
        if (o < mn) mn = o;
    }
    const float thr = unfkey(mn | 0x1FFFu) + MARGIN;

    const float* xt = g_xt + (size_t)tok * C_;
    float xr[8];
#pragma unroll
    for (int q = 0; q < 8; q++)
        xr[q] = xt[lane + 32 * q];

    float best_s = __uint_as_float(0x7F800000u);
    unsigned int best_j = 0xFFFFFFFFu;
#pragma unroll 1
    for (int r = 0; r < 8; r++) {
        float sf = unfkey(v[r] & 0xFFFFE000u);
        unsigned int m = __ballot_sync(0xFFFFFFFFu, sf <= thr);
        while (m) {
            int src = __ffs(m) - 1;
            m &= m - 1;
            uint32_t c = __shfl_sync(0xFFFFFFFFu, v[r], src);
            unsigned int j = c & 0x1FFFu;
            const float* row = cb + (size_t)j * C_;
            float dot = 0.0f;
#pragma unroll
            for (int q = 0; q < 8; q++)
                dot = fmaf(xr[q], row[lane + 32 * q], dot);
#pragma unroll
            for (int off = 16; off; off >>= 1)
                dot += __shfl_xor_sync(0xFFFFFFFFu, dot, off);
            float sc = fmaf(-2.0f, dot, g_cnorm[j]);
            if (sc < best_s || (sc == best_s && j < best_j)) {
                best_s = sc;
                best_j = j;
            }
        }
    }
    if (lane == 0) g_idx[tok] = best_j;
}

// ---------------------------------------------------------------------------
// Kernel 4: gather. One block per 32 tokens; staged codebook rows in smem.
__global__ void gather_kernel(const float* __restrict__ x,
                              const float* __restrict__ cb,
                              float* __restrict__ out) {
    __shared__ float qs[32][257];
    __shared__ float red[256];
    const int blk = blockIdx.x;
    const int tok0 = blk * 32;
    const int b = tok0 >> 10, hw0 = tok0 & 1023;
    const int tid = threadIdx.x;
    const int wid = tid >> 5, lane = tid & 31;

#pragma unroll 1
    for (int r = 0; r < 32; r++) {
        unsigned int idx = g_idx[tok0 + r];
        qs[r][tid] = cb[(size_t)idx * C_ + tid];
    }
    if (tid < 32) out[NQE + 1 + tok0 + tid] = (float)g_idx[tok0 + tid];
    __syncthreads();

    float lsum = 0.0f;
#pragma unroll
    for (int i = 0; i < 32; i++) {
        int c = wid * 32 + i;
        float q = qs[lane][c];
        size_t off = ((size_t)(b * C_ + c)) * HW_ + hw0 + lane;
        float dd = x[off] - q;
        lsum += dd * dd;
        out[off] = q;
    }
    red[tid] = lsum;
    __syncthreads();
#pragma unroll
    for (int s = 128; s; s >>= 1) {
        if (tid < s) red[tid] += red[tid + s];
        __syncthreads();
    }
    if (tid == 0) g_partial[blk] = red[0];
}

// Kernel 5: deterministic final loss reduction (512 partials)
__global__ void loss_kernel(float* __restrict__ out) {
    __shared__ float red[256];
    float s = 0.0f;
    for (int i = threadIdx.x; i < N_ / 32; i += 256) s += g_partial[i];
    red[threadIdx.x] = s;
    __syncthreads();
#pragma unroll
    for (int st = 128; st; st >>= 1) {
        if (threadIdx.x < st) red[threadIdx.x] += red[threadIdx.x + st];
        __syncthreads();
    }
    if (threadIdx.x == 0)
        out[NQE] = red[0] / (float)((size_t)N_ * C_);
}

// ---------------------------------------------------------------------------
extern "C" void kernel_launch(void* const* d_in, const int* in_sizes, int n_in,
                              void* d_out, int out_size) {
    const float* x  = (const float*)d_in[0];   // [16,256,32,32]
    const float* cb = (const float*)d_in[1];   // [8192,256]
    float* out = (float*)d_out;                // [qe | loss | indices]

    cudaFuncSetAttribute(argmin_mma_kernel,
                         cudaFuncAttributeMaxDynamicSharedMemorySize,
                         SMEM_BYTES);

    pconv_x_kernel<<<B_ * 128, 256>>>(x);
    pconv_cb_kernel<<<K_ / 8, 256>>>(cb);
    pconv_xt_kernel<<<B_ * 256, 256>>>(x);
    dim3 grid(N_ / TM, K_ / TN);
    argmin_mma_kernel<<<grid, 256, SMEM_BYTES>>>();
    rerank_kernel<<<N_ / 8, 256>>>(cb);
    gather_kernel<<<N_ / 32, 256>>>(x, cb, out);
    loss_kernel<<<1, 256>>>(out);
}

// round 16
// speedup vs baseline: 1.9675x; 1.0505x over previous
#include <cuda_runtime.h>
#include <cuda_fp16.h>
#include <cstdint>

// Problem constants
#define B_   16
#define C_   256
#define HW_  1024
#define K_   8192
#define N_   16384            // tokens
#define NQE  4194304          // qe elems

// Tiling
#define TM 128                 // tokens per CTA
#define TN 128                 // codes per CTA
#define KCH 32                 // K chunk (floats) = 16 k-pairs
#define NCHUNK (C_ / KCH)      // 8
#define NCAND 256              // candidates per token
#define MARGIN 3.5f            // rerank margin: fp16-accum noise + key truncation
#define NSTAGE 3

// smem (uint32 units). A: [kp][t] stride 136; B: [nr][kp] stride 20.
#define AST_A 136
#define A_U32 (16 * AST_A)             // 2176
#define BSTW 20
#define B_U32 (128 * BSTW)              // 2560
#define STAGE_U32 (A_U32 + B_U32)       // 4736
#define SMEM_BYTES (NSTAGE * STAGE_U32 * 4)  // 56832

// Scratch
__device__ uint32_t g_cand[(size_t)N_ * NCAND];             // 16MB packed keys
__device__ uint32_t g_xp[(size_t)B_ * 128 * HW_];           // 8MB  f16-pair x, [b][kp][t]
__device__ uint32_t g_cbp[(size_t)K_ * 128];                // 4MB  f16-pair cb, [n][kp]
__device__ float g_xt[(size_t)B_ * HW_ * C_];               // 16MB fp32 x, [b][hw][c]
__device__ unsigned int g_idx[N_];
__device__ float g_cnorm[K_];
__device__ float g_partial[N_ / 32];

__device__ __forceinline__ unsigned int fkey(float f) {
    unsigned int b = __float_as_uint(f);
    return (b & 0x80000000u) ? ~b : (b | 0x80000000u);
}
__device__ __forceinline__ float unfkey(unsigned int k) {
    unsigned int b = (k & 0x80000000u) ? (k & 0x7FFFFFFFu) : ~k;
    return __uint_as_float(b);
}
__device__ __forceinline__ uint32_t h_pair(float v0, float v1) {
    __half2 hp = __floats2half2_rn(v0, v1);
    return *(uint32_t*)&hp;
}
__device__ __forceinline__ uint32_t smem_u32(const void* p) {
    uint32_t a;
    asm("{ .reg .u64 t; cvta.to.shared.u64 t, %1; cvt.u32.u64 %0, t; }"
        : "=r"(a) : "l"(p));
    return a;
}
__device__ __forceinline__ void cp16(uint32_t dst, const void* src) {
    asm volatile("cp.async.cg.shared.global [%0], [%1], 16;"
                 :: "r"(dst), "l"(src));
}

#define MMA_F16ACC(D, A, B0, B1)                                            \
    asm volatile("mma.sync.aligned.m16n8k16.row.col.f16.f16.f16.f16 "       \
        "{%0,%1},{%2,%3,%4,%5},{%6,%7},{%0,%1};"                            \
        : "+r"((D)[0]), "+r"((D)[1])                                        \
        : "r"((A)[0]), "r"((A)[1]), "r"((A)[2]), "r"((A)[3]),               \
          "r"(B0), "r"(B1))

// ---------------------------------------------------------------------------
// Kernel 0a: preconvert x -> f16 pairs, layout [b][kp][t]
__global__ void pconv_x_kernel(const float* __restrict__ x) {
    const int blk = blockIdx.x;              // b*128 + kp
    const int b = blk >> 7, kp = blk & 127;
    const float4* r0 = (const float4*)(x + ((size_t)(b * C_ + 2 * kp)) * HW_);
    const float4* r1 = (const float4*)(x + ((size_t)(b * C_ + 2 * kp + 1)) * HW_);
    const int t4 = threadIdx.x;
    float4 a = r0[t4], c = r1[t4];
    uint4 o;
    o.x = h_pair(a.x, c.x);
    o.y = h_pair(a.y, c.y);
    o.z = h_pair(a.z, c.z);
    o.w = h_pair(a.w, c.w);
    ((uint4*)(g_xp + (size_t)blk * HW_))[t4] = o;
}

// Kernel 0b: preconvert codebook -> f16 pairs [n][kp], fused with cnorm.
__global__ void pconv_cb_kernel(const float* __restrict__ cb) {
    int code = blockIdx.x * 8 + (threadIdx.x >> 5);
    int lane = threadIdx.x & 31;
    const float4* row = (const float4*)(cb + (size_t)code * C_);
    uint2* orow = (uint2*)(g_cbp + (size_t)code * 128);
    float s = 0.0f;
#pragma unroll
    for (int r = 0; r < 2; r++) {
        float4 v = row[lane + 32 * r];
        s += v.x * v.x + v.y * v.y + v.z * v.z + v.w * v.w;
        uint2 p;
        p.x = h_pair(v.x, v.y);
        p.y = h_pair(v.z, v.w);
        orow[lane + 32 * r] = p;
    }
#pragma unroll
    for (int off = 16; off; off >>= 1)
        s += __shfl_xor_sync(0xFFFFFFFFu, s, off);
    if (lane == 0) g_cnorm[code] = s;
}

// Kernel 0c: transpose x -> fp32 [b][hw][c] (coalesced both sides).
__global__ void pconv_xt_kernel(const float* __restrict__ x) {
    __shared__ float sm[32][33];
    const int bx = blockIdx.x;
    const int b = bx >> 8;
    const int c0 = ((bx >> 5) & 7) * 32;
    const int hw0 = (bx & 31) * 32;
    const int tid = threadIdx.x;
    const int i = tid >> 5, j = tid & 31;
#pragma unroll
    for (int r = 0; r < 4; r++) {
        int row = i + 8 * r;
        sm[row][j] = x[((size_t)(b * C_ + c0 + row)) * HW_ + hw0 + j];
    }
    __syncthreads();
#pragma unroll
    for (int r = 0; r < 4; r++) {
        int row = i + 8 * r;
        g_xt[((size_t)(b * HW_ + hw0 + row)) * C_ + c0 + j] = sm[j][row];
    }
}

// ---------------------------------------------------------------------------
// Kernel 2: fp16 screening GEMM (fp16 accum), 3-stage pipeline with ONE
// __syncthreads per chunk, hoisted addressing. grid=(128,64), block=256.
__global__ void __launch_bounds__(256, 3)
argmin_mma_kernel() {
    extern __shared__ uint32_t smemu[];
    __shared__ float cnS[TN];

    const int tid = threadIdx.x;
    const int wid = tid >> 5;
    const int lane = tid & 31;
    const int g  = lane >> 2;
    const int tg = lane & 3;
    const int m0w = (wid & 3) * 32;
    const int n0w = (wid >> 2) * 64;

    const int n0tok = blockIdx.x * TM;
    const int b   = n0tok >> 10;
    const int hw0 = n0tok & 1023;
    const int j0  = blockIdx.y * TN;

    if (tid < TN) cnS[tid] = g_cnorm[j0 + tid];

    const uint32_t sbase = smem_u32(smemu);

    // hoisted per-thread fill addressing (loop-invariant)
    const int arow = tid >> 5, ac16 = tid & 31;
    const int bnr  = tid >> 2, bc4  = tid & 3;
    const uint32_t dstA0 = (uint32_t)(arow * (AST_A * 4) + ac16 * 16);
    const uint32_t dstA1 = dstA0 + (uint32_t)(8 * AST_A * 4);
    const uint32_t dstB0 = (uint32_t)(A_U32 * 4 + bnr * (BSTW * 4) + bc4 * 16);
    const uint32_t dstB1 = dstB0 + (uint32_t)(64 * BSTW * 4);
    const uint32_t* srcA0 = g_xp + (size_t)b * (128 * HW_) + hw0
                          + (size_t)arow * HW_ + ac16 * 4;          // +k*16*HW_
    const uint32_t* srcA1 = srcA0 + (size_t)8 * HW_;
    const uint32_t* srcB0 = g_cbp + (size_t)(j0 + bnr) * 128 + bc4 * 4;  // +k*16
    const uint32_t* srcB1 = srcB0 + (size_t)64 * 128;

    uint32_t d[2][8][2];
#pragma unroll
    for (int i = 0; i < 2; i++)
#pragma unroll
        for (int j = 0; j < 8; j++) {
            d[i][j][0] = 0u; d[i][j][1] = 0u;
        }

    auto fill = [&](int k, int stg) {
        uint32_t s0 = sbase + (uint32_t)(stg * STAGE_U32 * 4);
        size_t aoff = (size_t)k * (16 * HW_);
        int boff = k * 16;
        cp16(s0 + dstA0, srcA0 + aoff);
        cp16(s0 + dstA1, srcA1 + aoff);
        cp16(s0 + dstB0, srcB0 + boff);
        cp16(s0 + dstB1, srcB1 + boff);
        asm volatile("cp.async.commit_group;" ::: "memory");
    };

    auto mma_stage = [&](int stg) {
        const uint32_t* As = smemu + stg * STAGE_U32;
        const uint32_t* Bs = As + A_U32;
#pragma unroll
        for (int kk = 0; kk < 2; kk++) {
            const int kb = kk * 8 + tg;
            uint32_t ah[2][4];
#pragma unroll
            for (int dm = 0; dm < 2; dm++) {
                int mc = m0w + 16 * dm + g;
                ah[dm][0] = As[kb * AST_A + mc];
                ah[dm][1] = As[kb * AST_A + mc + 8];
                ah[dm][2] = As[(kb + 4) * AST_A + mc];
                ah[dm][3] = As[(kb + 4) * AST_A + mc + 8];
            }
#pragma unroll
            for (int dn = 0; dn < 8; dn++) {
                int nr = n0w + 8 * dn + g;
                uint32_t b0 = Bs[nr * BSTW + kb];
                uint32_t b1 = Bs[nr * BSTW + kb + 4];
                MMA_F16ACC(d[0][dn], ah[0], b0, b1);
                MMA_F16ACC(d[1][dn], ah[1], b0, b1);
            }
        }
    };

    fill(0, 0);
    fill(1, 1);
    // one __syncthreads per chunk: wait -> sync -> fill((k+2)%3) -> mma(k%3).
    // fill overwrites stage (k-1)%3, which every warp finished reading before
    // the sync (it was mma(k-1)'s stage).
#pragma unroll 1
    for (int k = 0; k < NCHUNK; k++) {
        asm volatile("cp.async.wait_group 1;" ::: "memory");
        __syncthreads();
        if (k + 2 < NCHUNK) fill(k + 2, (k + 2) % NSTAGE);
        else asm volatile("cp.async.commit_group;" ::: "memory");
        mma_stage(k % NSTAGE);
    }

    // epilogue: per n-warp top-2 per token row; packed 32-bit keys
#pragma unroll
    for (int dm = 0; dm < 2; dm++) {
#pragma unroll
        for (int h = 0; h < 2; h++) {
            uint32_t p1 = 0xFFFFFFFFu, p2 = 0xFFFFFFFFu;
#pragma unroll
            for (int dn = 0; dn < 8; dn++) {
                __half2 hp = *(__half2*)&d[dm][dn][h];
                float2 dv = __half22float2(hp);
#pragma unroll
                for (int e = 0; e < 2; e++) {
                    int col = n0w + 8 * dn + 2 * tg + e;
                    float sc = fmaf(-2.0f, e ? dv.y : dv.x, cnS[col]);
                    uint32_t p = (fkey(sc) & 0xFFFFE000u) |
                                 (uint32_t)(j0 + col);
                    if (p < p1) { p2 = p1; p1 = p; }
                    else if (p < p2) { p2 = p; }
                }
            }
#pragma unroll
            for (int off = 1; off <= 2; off <<= 1) {
                uint32_t q1 = __shfl_xor_sync(0xFFFFFFFFu, p1, off);
                uint32_t q2 = __shfl_xor_sync(0xFFFFFFFFu, p2, off);
                if (q1 < p1) { p2 = (p1 < q2) ? p1 : q2; p1 = q1; }
                else         { p2 = (p2 < q1) ? p2 : q1; }
            }
            if (tg == 0) {
                int tok = n0tok + m0w + 16 * dm + 8 * h + g;
                size_t base = (size_t)tok * NCAND + blockIdx.y * 4 + (wid >> 2) * 2;
                g_cand[base] = p1;
                g_cand[base + 1] = p2;
            }
        }
    }
}

// ---------------------------------------------------------------------------
// Kernel 3: exact fp32 rerank. One warp per token; coalesced x via g_xt.
__global__ void __launch_bounds__(256)
rerank_kernel(const float* __restrict__ cb) {
    const int wid = threadIdx.x >> 5;
    const int lane = threadIdx.x & 31;
    const int tok = blockIdx.x * 8 + wid;
    const uint32_t* cand = g_cand + (size_t)tok * NCAND;

    uint32_t v[8];
    uint32_t mn = 0xFFFFFFFFu;
#pragma unroll
    for (int r = 0; r < 8; r++) {
        v[r] = cand[lane + 32 * r];
        if (v[r] < mn) mn = v[r];
    }
#pragma unroll
    for (int off = 16; off; off >>= 1) {
        uint32_t o = __shfl_xor_sync(0xFFFFFFFFu, mn, off);
        if (o < mn) mn = o;
    }
    const float thr = unfkey(mn | 0x1FFFu) + MARGIN;

    const float* xt = g_xt + (size_t)tok * C_;
    float xr[8];
#pragma unroll
    for (int q = 0; q < 8; q++)
        xr[q] = xt[lane + 32 * q];

    float best_s = __uint_as_float(0x7F800000u);
    unsigned int best_j = 0xFFFFFFFFu;
#pragma unroll 1
    for (int r = 0; r < 8; r++) {
        float sf = unfkey(v[r] & 0xFFFFE000u);
        unsigned int m = __ballot_sync(0xFFFFFFFFu, sf <= thr);
        while (m) {
            int src = __ffs(m) - 1;
            m &= m - 1;
            uint32_t c = __shfl_sync(0xFFFFFFFFu, v[r], src);
            unsigned int j = c & 0x1FFFu;
            const float* row = cb + (size_t)j * C_;
            float dot = 0.0f;
#pragma unroll
            for (int q = 0; q < 8; q++)
                dot = fmaf(xr[q], row[lane + 32 * q], dot);
#pragma unroll
            for (int off = 16; off; off >>= 1)
                dot += __shfl_xor_sync(0xFFFFFFFFu, dot, off);
            float sc = fmaf(-2.0f, dot, g_cnorm[j]);
            if (sc < best_s || (sc == best_s && j < best_j)) {
                best_s = sc;
                best_j = j;
            }
        }
    }
    if (lane == 0) g_idx[tok] = best_j;
}

// ---------------------------------------------------------------------------
// Kernel 4: gather. One block per 32 tokens; staged codebook rows in smem.
__global__ void gather_kernel(const float* __restrict__ x,
                              const float* __restrict__ cb,
                              float* __restrict__ out) {
    __shared__ float qs[32][257];
    __shared__ float red[256];
    const int blk = blockIdx.x;
    const int tok0 = blk * 32;
    const int b = tok0 >> 10, hw0 = tok0 & 1023;
    const int tid = threadIdx.x;
    const int wid = tid >> 5, lane = tid & 31;

#pragma unroll 1
    for (int r = 0; r < 32; r++) {
        unsigned int idx = g_idx[tok0 + r];
        qs[r][tid] = cb[(size_t)idx * C_ + tid];
    }
    if (tid < 32) out[NQE + 1 + tok0 + tid] = (float)g_idx[tok0 + tid];
    __syncthreads();

    float lsum = 0.0f;
#pragma unroll
    for (int i = 0; i < 32; i++) {
        int c = wid * 32 + i;
        float q = qs[lane][c];
        size_t off = ((size_t)(b * C_ + c)) * HW_ + hw0 + lane;
        float dd = x[off] - q;
        lsum += dd * dd;
        out[off] = q;
    }
    red[tid] = lsum;
    __syncthreads();
#pragma unroll
    for (int s = 128; s; s >>= 1) {
        if (tid < s) red[tid] += red[tid + s];
        __syncthreads();
    }
    if (tid == 0) g_partial[blk] = red[0];
}

// Kernel 5: deterministic final loss reduction (512 partials)
__global__ void loss_kernel(float* __restrict__ out) {
    __shared__ float red[256];
    float s = 0.0f;
    for (int i = threadIdx.x; i < N_ / 32; i += 256) s += g_partial[i];
    red[threadIdx.x] = s;
    __syncthreads();
#pragma unroll
    for (int st = 128; st; st >>= 1) {
        if (threadIdx.x < st) red[threadIdx.x] += red[threadIdx.x + st];
        __syncthreads();
    }
    if (threadIdx.x == 0)
        out[NQE] = red[0] / (float)((size_t)N_ * C_);
}

// ---------------------------------------------------------------------------
extern "C" void kernel_launch(void* const* d_in, const int* in_sizes, int n_in,
                              void* d_out, int out_size) {
    const float* x  = (const float*)d_in[0];   // [16,256,32,32]
    const float* cb = (const float*)d_in[1];   // [8192,256]
    float* out = (float*)d_out;                // [qe | loss | indices]

    cudaFuncSetAttribute(argmin_mma_kernel,
                         cudaFuncAttributeMaxDynamicSharedMemorySize,
                         SMEM_BYTES);

    pconv_x_kernel<<<B_ * 128, 256>>>(x);
    pconv_cb_kernel<<<K_ / 8, 256>>>(cb);
    pconv_xt_kernel<<<B_ * 256, 256>>>(x);
    dim3 grid(N_ / TM, K_ / TN);
    argmin_mma_kernel<<<grid, 256, SMEM_BYTES>>>();
    rerank_kernel<<<N_ / 8, 256>>>(cb);
    gather_kernel<<<N_ / 32, 256>>>(x, cb, out);
    loss_kernel<<<1, 256>>>(out);
}